// round 10
// baseline (speedup 1.0000x reference)
#include <cuda_runtime.h>
#include <cstdint>
#include <math.h>

#define H_IN    24
#define F       50
#define FP      52      // padded feature stride (52*4=208 bytes, 16B aligned)
#define DH      100
#define DT      0.0625f
#define SQDT    0.25f
#define SIG     5.0f

// ---------------- packed f32x2 helpers (Blackwell FFMA2 path) ----------------
__device__ __forceinline__ uint64_t pack2(float lo, float hi) {
    uint64_t r;
    asm("mov.b64 %0, {%1, %2};" : "=l"(r) : "f"(lo), "f"(hi));
    return r;
}
__device__ __forceinline__ float2 unpack2(uint64_t v) {
    float2 r;
    asm("mov.b64 {%0, %1}, %2;" : "=f"(r.x), "=f"(r.y) : "l"(v));
    return r;
}
__device__ __forceinline__ void ffma2(uint64_t& d, uint64_t a, uint64_t b) {
    asm("fma.rn.f32x2 %0, %1, %2, %0;" : "+l"(d) : "l"(a), "l"(b));
}

// integer add on the FMA pipe: d = a*one + b, `one` opaque (==1)
__device__ __forceinline__ uint32_t imad1(uint32_t a, uint32_t one, uint32_t b) {
    uint32_t d;
    asm("mad.lo.u32 %0, %1, %2, %3;" : "=r"(d) : "r"(a), "r"(one), "r"(b));
    return d;
}

// rotate-left-by-r then xor: IMAD.WIDE (fma pipe) + one LOP3 (alu):
// mul.wide.u32 v*(1<<r) -> lo = v<<r, hi = v>>(32-r); out = (lo|hi)^x  [LUT 0x56]
__device__ __forceinline__ uint32_t rotw_xor(uint32_t v, uint32_t m, uint32_t x) {
    uint32_t out;
    asm("{\n\t"
        ".reg .b64 t;\n\t"
        ".reg .b32 lo, hi;\n\t"
        "mul.wide.u32 t, %1, %2;\n\t"
        "mov.b64 {lo, hi}, t;\n\t"
        "lop3.b32 %0, lo, hi, %3, 0x56;\n\t"
        "}"
        : "=r"(out) : "r"(v), "r"(m), "r"(x));
    return out;
}

struct RotM { uint32_t m13, m15, m26, m6, m17, m29, m16, m24; };

// ---------------- Threefry-2x32 (matches JAX) ----------------
__device__ __forceinline__ void tf_round(uint32_t& x0, uint32_t& x1, int r) {
    x0 += x1;
    x1 = __funnelshift_l(x1, x1, r);
    x1 ^= x0;
}

// Full threefry (used for fold_in key derivation)
__device__ __forceinline__ void threefry2x32(uint32_t k0, uint32_t k1,
                                             uint32_t c0, uint32_t c1,
                                             uint32_t& o0, uint32_t& o1) {
    uint32_t k2 = k0 ^ k1 ^ 0x1BD11BDAu;
    uint32_t x0 = c0 + k0, x1 = c1 + k1;
    tf_round(x0,x1,13); tf_round(x0,x1,15); tf_round(x0,x1,26); tf_round(x0,x1, 6);
    x0 += k1; x1 += k2 + 1u;
    tf_round(x0,x1,17); tf_round(x0,x1,29); tf_round(x0,x1,16); tf_round(x0,x1,24);
    x0 += k2; x1 += k0 + 2u;
    tf_round(x0,x1,13); tf_round(x0,x1,15); tf_round(x0,x1,26); tf_round(x0,x1, 6);
    x0 += k0; x1 += k1 + 3u;
    tf_round(x0,x1,17); tf_round(x0,x1,29); tf_round(x0,x1,16); tf_round(x0,x1,24);
    x0 += k1; x1 += k2 + 4u;
    tf_round(x0,x1,13); tf_round(x0,x1,15); tf_round(x0,x1,26); tf_round(x0,x1, 6);
    o0 = x0 + k2;
    o1 = x1 + k0 + 5u;
}

// ---- chain b0: pure-alu version (SHF rotations), hoisted key constants ----
__device__ __forceinline__ uint32_t tf_bits_alu(uint32_t k0, uint32_t k1, uint32_t k2,
                                                uint32_t kb1, uint32_t kb2, uint32_t kb3,
                                                uint32_t kb4, uint32_t kb5,
                                                uint32_t x1_init) {
    uint32_t x0 = k0;
    uint32_t x1 = x1_init;                       // (cbase + f) + k1
    tf_round(x0,x1,13); tf_round(x0,x1,15); tf_round(x0,x1,26); tf_round(x0,x1, 6);
    x0 += k1; x1 += kb1;
    tf_round(x0,x1,17); tf_round(x0,x1,29); tf_round(x0,x1,16); tf_round(x0,x1,24);
    x0 += k2; x1 += kb2;
    tf_round(x0,x1,13); tf_round(x0,x1,15); tf_round(x0,x1,26); tf_round(x0,x1, 6);
    x0 += k0; x1 += kb3;
    tf_round(x0,x1,17); tf_round(x0,x1,29); tf_round(x0,x1,16); tf_round(x0,x1,24);
    x0 += k1; x1 += kb4;
    tf_round(x0,x1,13); tf_round(x0,x1,15); tf_round(x0,x1,26); tf_round(x0,x1, 6);
    return (x0 + k2) ^ (x1 + kb5);
}

// ---- chain b1: fma-heavy version (IMAD.WIDE rotations, IMAD adds) ----
__device__ __forceinline__ void tfw_round(uint32_t& x0, uint32_t& x1, uint32_t m,
                                          uint32_t one) {
    x0 = imad1(x0, one, x1);            // fma pipe
    x1 = rotw_xor(x1, m, x0);           // fma (wide mul) + alu (lop3)
}
__device__ __forceinline__ uint32_t tf_bits_fma(uint32_t k0, uint32_t k1, uint32_t k2,
                                                uint32_t kb1, uint32_t kb2, uint32_t kb3,
                                                uint32_t kb4, uint32_t kb5,
                                                uint32_t x1_init, const RotM& R,
                                                uint32_t one) {
    uint32_t x0 = k0;
    uint32_t x1 = x1_init;
    tfw_round(x0,x1,R.m13,one); tfw_round(x0,x1,R.m15,one);
    tfw_round(x0,x1,R.m26,one); tfw_round(x0,x1,R.m6, one);
    x0 = imad1(x0, one, k1); x1 = imad1(x1, one, kb1);
    tfw_round(x0,x1,R.m17,one); tfw_round(x0,x1,R.m29,one);
    tfw_round(x0,x1,R.m16,one); tfw_round(x0,x1,R.m24,one);
    x0 = imad1(x0, one, k2); x1 = imad1(x1, one, kb2);
    tfw_round(x0,x1,R.m13,one); tfw_round(x0,x1,R.m15,one);
    tfw_round(x0,x1,R.m26,one); tfw_round(x0,x1,R.m6, one);
    x0 = imad1(x0, one, k0); x1 = imad1(x1, one, kb3);
    tfw_round(x0,x1,R.m17,one); tfw_round(x0,x1,R.m29,one);
    tfw_round(x0,x1,R.m16,one); tfw_round(x0,x1,R.m24,one);
    x0 = imad1(x0, one, k1); x1 = imad1(x1, one, kb4);
    tfw_round(x0,x1,R.m13,one); tfw_round(x0,x1,R.m15,one);
    tfw_round(x0,x1,R.m26,one); tfw_round(x0,x1,R.m6, one);
    return imad1(x0, one, k2) ^ imad1(x1, one, kb5);
}

// XLA ErfInv f32 (Giles polynomial), with cheap factored log:
// w = -log(1-x^2) = -log((1-x)(1+x)); 1±x are (near-)exact by Sterbenz.
__device__ __forceinline__ float xla_erfinv_fast(float x) {
    float w = -__logf((1.0f - x) * (1.0f + x));
    float p;
    if (w < 5.0f) {
        w = w - 2.5f;
        p = 2.81022636e-08f;
        p = fmaf(p, w, 3.43273939e-07f);
        p = fmaf(p, w, -3.5233877e-06f);
        p = fmaf(p, w, -4.39150654e-06f);
        p = fmaf(p, w, 0.00021858087f);
        p = fmaf(p, w, -0.00125372503f);
        p = fmaf(p, w, -0.00417768164f);
        p = fmaf(p, w, 0.246640727f);
        p = fmaf(p, w, 1.50140941f);
    } else {
        w = sqrtf(w) - 3.0f;
        p = -0.000200214257f;
        p = fmaf(p, w, 0.000100950558f);
        p = fmaf(p, w, 0.00134934322f);
        p = fmaf(p, w, -0.00367342844f);
        p = fmaf(p, w, 0.00573950773f);
        p = fmaf(p, w, -0.0076224613f);
        p = fmaf(p, w, 0.00943887047f);
        p = fmaf(p, w, 1.00167406f);
        p = fmaf(p, w, 2.83297682f);
    }
    return p * x;
}

// bits -> N(0,1); the JAX lower clamp fmaxf(u, -0.99999994) is a provable
// no-op (u >= -0.99999994 for all r >= 0, fmaf monotone) and is deleted.
__device__ __forceinline__ float bits_to_normal(uint32_t bits) {
    float r = __uint_as_float(0x3f800000u | (bits >> 9)) - 1.0f;   // [0,1)
    float u = fmaf(r, 2.0f, -0.99999994f);
    return 1.41421356f * xla_erfinv_fast(u);
}

__global__ void __launch_bounds__(128, 3)
sde_kernel(const float* __restrict__ x,
           const float* __restrict__ W_down,  const float* __restrict__ b_down,
           const float* __restrict__ W_drift, const float* __restrict__ b_drift,
           const float* __restrict__ W_diff1, const float* __restrict__ b_diff1,
           const float* __restrict__ W_diff2, const float* __restrict__ b_diff2,
           const float* __restrict__ W_fc,    const float* __restrict__ b_fc,
           float* __restrict__ out, int N)
{
    __shared__ __align__(16) float sWdown[H_IN * FP];
    __shared__ __align__(16) float sWd[F * FP];
    __shared__ __align__(16) float sW1T[DH * FP];  // transposed diff1: [m][j]
    __shared__ __align__(16) float sW2[DH];
    __shared__ __align__(16) float sB1[DH];
    __shared__ __align__(16) float sBdown[FP];
    __shared__ __align__(16) float sBdrift[FP];
    __shared__ __align__(16) float sWfc[2 * F];    // [k*2+c]
    __shared__ uint32_t sK0[64], sK1[64];
    __shared__ uint32_t sRotM[8];                  // opaque (1u<<r)
    __shared__ uint32_t sOne;                      // opaque 1

    const int tid = threadIdx.x;

    for (int idx = tid; idx < H_IN * FP; idx += blockDim.x) {
        int h = idx / FP, k = idx - h * FP;
        sWdown[idx] = (k < F) ? W_down[h * F + k] : 0.0f;
    }
    for (int idx = tid; idx < F * FP; idx += blockDim.x) {
        int j = idx / FP, k = idx - j * FP;
        sWd[idx] = (k < F) ? W_drift[j * F + k] : 0.0f;
    }
    for (int idx = tid; idx < DH * FP; idx += blockDim.x) {
        int m = idx / FP, j = idx - m * FP;
        sW1T[idx] = (j < F) ? W_diff1[j * DH + m] : 0.0f;
    }
    for (int idx = tid; idx < DH; idx += blockDim.x) {
        sW2[idx] = W_diff2[idx];
        sB1[idx] = b_diff1[idx];
        sWfc[idx] = W_fc[idx];
    }
    for (int idx = tid; idx < FP; idx += blockDim.x) {
        sBdown[idx]  = (idx < F) ? b_down[idx]  : 0.0f;
        sBdrift[idx] = (idx < F) ? b_drift[idx] : 0.0f;
    }
    // per-step fold_in keys: threefry((0,42), (0,i))
    if (tid < 64) {
        uint32_t a, b;
        threefry2x32(0u, 42u, 0u, (uint32_t)tid, a, b);
        sK0[tid] = a; sK1[tid] = b;
    }
    if (tid < 8) {
        const int rots[8] = {13, 15, 26, 6, 17, 29, 16, 24};
        sRotM[tid] = 1u << rots[tid];
    }
    if (tid == 0) sOne = 1u;
    __syncthreads();

    const uint32_t t = blockIdx.x * blockDim.x + tid;   // one token per thread
    if (t >= (uint32_t)N) return;
    const uint32_t cbase = t * 50u;                     // flattened sample base
    const uint32_t one = sOne;

    RotM R;
    R.m13 = sRotM[0]; R.m15 = sRotM[1]; R.m26 = sRotM[2]; R.m6  = sRotM[3];
    R.m17 = sRotM[4]; R.m29 = sRotM[5]; R.m16 = sRotM[6]; R.m24 = sRotM[7];

    // ---- state o lives permanently packed: op[q] = (o[2q], o[2q+1]) ----
    uint64_t op[26];
    float coef;
    {
        // downsample: o = x @ W_down + b_down (packed f32x2)
        {
            const ulonglong2* bb = reinterpret_cast<const ulonglong2*>(sBdown);
            #pragma unroll
            for (int q = 0; q < 13; q++) {
                ulonglong2 b2 = bb[q];
                op[2*q] = b2.x; op[2*q+1] = b2.y;
            }
        }
        const float* xp = x + (size_t)t * H_IN;
        #pragma unroll
        for (int h = 0; h < H_IN; h++) {
            float xv = __ldg(xp + h);
            uint64_t xvv = pack2(xv, xv);
            const ulonglong2* wrow = reinterpret_cast<const ulonglong2*>(&sWdown[h * FP]);
            #pragma unroll
            for (int q = 0; q < 13; q++) {
                ulonglong2 w = wrow[q];
                ffma2(op[2*q],   xvv, w.x);
                ffma2(op[2*q+1], xvv, w.y);
            }
        }

        // diffusion net at t=0: coef = SIGMA*sigmoid(relu(o@W1+b1)@W2+b2)*sqrt(dt)
        float ds = __ldg(b_diff2);
        #pragma unroll 4
        for (int m = 0; m < DH; m++) {
            uint64_t sp = pack2(sB1[m], 0.0f);
            const ulonglong2* wrow = reinterpret_cast<const ulonglong2*>(&sW1T[m * FP]);
            #pragma unroll
            for (int q = 0; q < 13; q++) {
                ulonglong2 w = wrow[q];
                ffma2(sp, op[2*q],   w.x);
                ffma2(sp, op[2*q+1], w.y);
            }
            float2 sv = unpack2(sp);
            float s = sv.x + sv.y;
            ds = fmaf(fmaxf(s, 0.0f), sW2[m], ds);
        }
        coef = SIG * (1.0f / (1.0f + expf(-ds))) * SQDT;
    }

    const uint64_t DT2   = pack2(DT, DT);
    const uint64_t coef2 = pack2(coef, coef);

    // ---- 64 SDE steps ----
    for (int i = 0; i < 64; i++) {
        const uint32_t fk0 = sK0[i], fk1 = sK1[i];
        const uint32_t fk2 = fk0 ^ fk1 ^ 0x1BD11BDAu;
        const uint32_t kb1 = fk2 + 1u, kb2 = fk0 + 2u, kb3 = fk1 + 3u,
                       kb4 = fk2 + 4u, kb5 = fk0 + 5u;
        const uint32_t x1base = cbase + fk1;     // x1_init = (cbase+f) + k1

        // drift pre-activation (packed): accp = o @ W_drift + b_drift
        uint64_t accp[26];
        {
            const ulonglong2* bb = reinterpret_cast<const ulonglong2*>(sBdrift);
            #pragma unroll
            for (int q = 0; q < 13; q++) {
                ulonglong2 b2 = bb[q];
                accp[2*q] = b2.x; accp[2*q+1] = b2.y;
            }
        }
        #pragma unroll 5
        for (int jq = 0; jq < 25; jq++) {           // feature pair (2jq, 2jq+1)
            float2 ov = unpack2(op[jq]);
            uint64_t o0 = pack2(ov.x, ov.x);
            uint64_t o1 = pack2(ov.y, ov.y);
            const ulonglong2* w0 = reinterpret_cast<const ulonglong2*>(&sWd[(2*jq)   * FP]);
            const ulonglong2* w1 = reinterpret_cast<const ulonglong2*>(&sWd[(2*jq+1) * FP]);
            #pragma unroll
            for (int q = 0; q < 13; q++) {
                ulonglong2 wa = w0[q];
                ulonglong2 wb = w1[q];
                ffma2(accp[2*q],   o0, wa.x);
                ffma2(accp[2*q+1], o0, wa.y);
                ffma2(accp[2*q],   o1, wb.x);
                ffma2(accp[2*q+1], o1, wb.y);
            }
        }

        // noise + packed update: chain b0 on alu pipe, chain b1 on fma pipe
        #pragma unroll 5
        for (int q = 0; q < 25; q++) {
            uint32_t b0 = tf_bits_alu(fk0, fk1, fk2, kb1, kb2, kb3, kb4, kb5,
                                      x1base + (uint32_t)(2*q));
            uint32_t b1 = tf_bits_fma(fk0, fk1, fk2, kb1, kb2, kb3, kb4, kb5,
                                      x1base + (uint32_t)(2*q) + 1u, R, one);
            float z0 = bits_to_normal(b0);
            float z1 = bits_to_normal(b1);
            float2 a = unpack2(accp[q]);
            uint64_t ap = pack2(fmaxf(a.x, 0.0f), fmaxf(a.y, 0.0f));
            ffma2(op[q], ap, DT2);
            uint64_t zp = pack2(z0, z1);
            ffma2(op[q], zp, coef2);
        }
    }

    // ---- head: final = relu(o) @ W_fc + b_fc; mu, softplus(sigma)+1e-3 ----
    float mu = __ldg(b_fc + 0);
    float sg = __ldg(b_fc + 1);
    #pragma unroll
    for (int q = 0; q < 25; q++) {
        float2 ov = unpack2(op[q]);
        float r0 = fmaxf(ov.x, 0.0f);
        float r1 = fmaxf(ov.y, 0.0f);
        mu = fmaf(r0, sWfc[4*q],     mu);
        sg = fmaf(r0, sWfc[4*q + 1], sg);
        mu = fmaf(r1, sWfc[4*q + 2], mu);
        sg = fmaf(r1, sWfc[4*q + 3], sg);
    }
    float sigma = fmaxf(sg, 0.0f) + log1pf(expf(-fabsf(sg))) + 0.001f;

    out[t] = mu;
    out[(size_t)N + t] = sigma;
}

extern "C" void kernel_launch(void* const* d_in, const int* in_sizes, int n_in,
                              void* d_out, int out_size)
{
    const float* x       = (const float*)d_in[0];
    const float* W_down  = (const float*)d_in[1];
    const float* b_down  = (const float*)d_in[2];
    const float* W_drift = (const float*)d_in[3];
    const float* b_drift = (const float*)d_in[4];
    const float* W_diff1 = (const float*)d_in[5];
    const float* b_diff1 = (const float*)d_in[6];
    const float* W_diff2 = (const float*)d_in[7];
    const float* b_diff2 = (const float*)d_in[8];
    const float* W_fc    = (const float*)d_in[9];
    const float* b_fc    = (const float*)d_in[10];

    int N = in_sizes[0] / H_IN;          // number of tokens (B*L)
    int threads = 128;
    int blocks = (N + threads - 1) / threads;

    sde_kernel<<<blocks, threads>>>(x, W_down, b_down, W_drift, b_drift,
                                    W_diff1, b_diff1, W_diff2, b_diff2,
                                    W_fc, b_fc, (float*)d_out, N);
}

// round 11
// speedup vs baseline: 1.1115x; 1.1115x over previous
#include <cuda_runtime.h>
#include <cstdint>
#include <math.h>

#define H_IN    24
#define F       50
#define FP      52      // padded feature stride (52*4=208 bytes, 16B aligned)
#define DH      100
#define DT      0.0625f
#define SQDT    0.25f
#define SIG     5.0f

// ---------------- packed f32x2 helpers (Blackwell FFMA2 path) ----------------
__device__ __forceinline__ uint64_t pack2(float lo, float hi) {
    uint64_t r;
    asm("mov.b64 %0, {%1, %2};" : "=l"(r) : "f"(lo), "f"(hi));
    return r;
}
__device__ __forceinline__ float2 unpack2(uint64_t v) {
    float2 r;
    asm("mov.b64 {%0, %1}, %2;" : "=f"(r.x), "=f"(r.y) : "l"(v));
    return r;
}
__device__ __forceinline__ void ffma2(uint64_t& d, uint64_t a, uint64_t b) {
    asm("fma.rn.f32x2 %0, %1, %2, %0;" : "+l"(d) : "l"(a), "l"(b));
}

__device__ __forceinline__ float fast_sqrtf(float x) {
    float r;
    asm("sqrt.approx.f32 %0, %1;" : "=f"(r) : "f"(x));
    return r;
}

// ---------------- Threefry-2x32 (matches JAX) ----------------
__device__ __forceinline__ void tf_round(uint32_t& x0, uint32_t& x1, int r) {
    x0 += x1;
    x1 = __funnelshift_l(x1, x1, r);
    x1 ^= x0;
}

// Full threefry (used for fold_in key derivation)
__device__ __forceinline__ void threefry2x32(uint32_t k0, uint32_t k1,
                                             uint32_t c0, uint32_t c1,
                                             uint32_t& o0, uint32_t& o1) {
    uint32_t k2 = k0 ^ k1 ^ 0x1BD11BDAu;
    uint32_t x0 = c0 + k0, x1 = c1 + k1;
    tf_round(x0,x1,13); tf_round(x0,x1,15); tf_round(x0,x1,26); tf_round(x0,x1, 6);
    x0 += k1; x1 += k2 + 1u;
    tf_round(x0,x1,17); tf_round(x0,x1,29); tf_round(x0,x1,16); tf_round(x0,x1,24);
    x0 += k2; x1 += k0 + 2u;
    tf_round(x0,x1,13); tf_round(x0,x1,15); tf_round(x0,x1,26); tf_round(x0,x1, 6);
    x0 += k0; x1 += k1 + 3u;
    tf_round(x0,x1,17); tf_round(x0,x1,29); tf_round(x0,x1,16); tf_round(x0,x1,24);
    x0 += k1; x1 += k2 + 4u;
    tf_round(x0,x1,13); tf_round(x0,x1,15); tf_round(x0,x1,26); tf_round(x0,x1, 6);
    o0 = x0 + k2;
    o1 = x1 + k0 + 5u;
}

// Partitionable-mode random bits for sample index j (< 2^32):
// counter = (0, j); bits = out0 ^ out1. c0 = 0 folded in (x0 starts at k0).
// kb1..kb5 hoisted per-step key-injection constants. Pure alu-pipe version.
__device__ __forceinline__ uint32_t tf_bits(uint32_t k0, uint32_t k1, uint32_t k2,
                                            uint32_t kb1, uint32_t kb2, uint32_t kb3,
                                            uint32_t kb4, uint32_t kb5,
                                            uint32_t x1_init) {
    uint32_t x0 = k0;
    uint32_t x1 = x1_init;                       // (cbase + f) + k1
    tf_round(x0,x1,13); tf_round(x0,x1,15); tf_round(x0,x1,26); tf_round(x0,x1, 6);
    x0 += k1; x1 += kb1;
    tf_round(x0,x1,17); tf_round(x0,x1,29); tf_round(x0,x1,16); tf_round(x0,x1,24);
    x0 += k2; x1 += kb2;
    tf_round(x0,x1,13); tf_round(x0,x1,15); tf_round(x0,x1,26); tf_round(x0,x1, 6);
    x0 += k0; x1 += kb3;
    tf_round(x0,x1,17); tf_round(x0,x1,29); tf_round(x0,x1,16); tf_round(x0,x1,24);
    x0 += k1; x1 += kb4;
    tf_round(x0,x1,13); tf_round(x0,x1,15); tf_round(x0,x1,26); tf_round(x0,x1, 6);
    return (x0 + k2) ^ (x1 + kb5);
}

// bits -> erfinv(u)*u-scaled normal, BRANCHLESS (both arms + FSEL).
// The sqrt(2) factor and the coef multiply are folded into coef2 outside.
// XLA ErfInv Giles polynomial; w = -log((1-u)(1+u)) (Sterbenz-exact factors).
// JAX lower clamp on u is a provable no-op and removed (validated R10).
__device__ __forceinline__ float bits_to_normal_noscale(uint32_t bits) {
    float r = __uint_as_float(0x3f800000u | (bits >> 9)) - 1.0f;   // [0,1)
    float u = fmaf(r, 2.0f, -0.99999994f);
    float w = -__logf((1.0f - u) * (1.0f + u));
    // common arm (w < 5)
    float wa = w - 2.5f;
    float pa = 2.81022636e-08f;
    pa = fmaf(pa, wa, 3.43273939e-07f);
    pa = fmaf(pa, wa, -3.5233877e-06f);
    pa = fmaf(pa, wa, -4.39150654e-06f);
    pa = fmaf(pa, wa, 0.00021858087f);
    pa = fmaf(pa, wa, -0.00125372503f);
    pa = fmaf(pa, wa, -0.00417768164f);
    pa = fmaf(pa, wa, 0.246640727f);
    pa = fmaf(pa, wa, 1.50140941f);
    // rare arm (w >= 5)
    float wb = fast_sqrtf(w) - 3.0f;
    float pb = -0.000200214257f;
    pb = fmaf(pb, wb, 0.000100950558f);
    pb = fmaf(pb, wb, 0.00134934322f);
    pb = fmaf(pb, wb, -0.00367342844f);
    pb = fmaf(pb, wb, 0.00573950773f);
    pb = fmaf(pb, wb, -0.0076224613f);
    pb = fmaf(pb, wb, 0.00943887047f);
    pb = fmaf(pb, wb, 1.00167406f);
    pb = fmaf(pb, wb, 2.83297682f);
    float p = (w < 5.0f) ? pa : pb;     // FSEL, no branch
    return p * u;                        // z / sqrt(2); sqrt2 folded into coef
}

__global__ void __launch_bounds__(128, 3)
sde_kernel(const float* __restrict__ x,
           const float* __restrict__ W_down,  const float* __restrict__ b_down,
           const float* __restrict__ W_drift, const float* __restrict__ b_drift,
           const float* __restrict__ W_diff1, const float* __restrict__ b_diff1,
           const float* __restrict__ W_diff2, const float* __restrict__ b_diff2,
           const float* __restrict__ W_fc,    const float* __restrict__ b_fc,
           float* __restrict__ out, int N)
{
    __shared__ __align__(16) float sWdown[H_IN * FP];
    __shared__ __align__(16) float sWd[F * FP];
    __shared__ __align__(16) float sW1T[DH * FP];  // transposed diff1: [m][j]
    __shared__ __align__(16) float sW2[DH];
    __shared__ __align__(16) float sB1[DH];
    __shared__ __align__(16) float sBdown[FP];
    __shared__ __align__(16) float sBdrift[FP];
    __shared__ __align__(16) float sWfc[2 * F];    // [k*2+c]
    __shared__ uint32_t sK0[64], sK1[64];

    const int tid = threadIdx.x;

    for (int idx = tid; idx < H_IN * FP; idx += blockDim.x) {
        int h = idx / FP, k = idx - h * FP;
        sWdown[idx] = (k < F) ? W_down[h * F + k] : 0.0f;
    }
    for (int idx = tid; idx < F * FP; idx += blockDim.x) {
        int j = idx / FP, k = idx - j * FP;
        sWd[idx] = (k < F) ? W_drift[j * F + k] : 0.0f;
    }
    for (int idx = tid; idx < DH * FP; idx += blockDim.x) {
        int m = idx / FP, j = idx - m * FP;
        sW1T[idx] = (j < F) ? W_diff1[j * DH + m] : 0.0f;
    }
    for (int idx = tid; idx < DH; idx += blockDim.x) {
        sW2[idx] = W_diff2[idx];
        sB1[idx] = b_diff1[idx];
        sWfc[idx] = W_fc[idx];
    }
    for (int idx = tid; idx < FP; idx += blockDim.x) {
        sBdown[idx]  = (idx < F) ? b_down[idx]  : 0.0f;
        sBdrift[idx] = (idx < F) ? b_drift[idx] : 0.0f;
    }
    // per-step fold_in keys: threefry((0,42), (0,i))
    if (tid < 64) {
        uint32_t a, b;
        threefry2x32(0u, 42u, 0u, (uint32_t)tid, a, b);
        sK0[tid] = a; sK1[tid] = b;
    }
    __syncthreads();

    const uint32_t t = blockIdx.x * blockDim.x + tid;   // one token per thread
    if (t >= (uint32_t)N) return;
    const uint32_t cbase = t * 50u;                     // flattened sample base

    // ---- state o lives permanently packed: op[q] = (o[2q], o[2q+1]) ----
    uint64_t op[26];
    float coef;
    {
        // downsample: o = x @ W_down + b_down (packed f32x2)
        {
            const ulonglong2* bb = reinterpret_cast<const ulonglong2*>(sBdown);
            #pragma unroll
            for (int q = 0; q < 13; q++) {
                ulonglong2 b2 = bb[q];
                op[2*q] = b2.x; op[2*q+1] = b2.y;
            }
        }
        const float* xp = x + (size_t)t * H_IN;
        #pragma unroll
        for (int h = 0; h < H_IN; h++) {
            float xv = __ldg(xp + h);
            uint64_t xvv = pack2(xv, xv);
            const ulonglong2* wrow = reinterpret_cast<const ulonglong2*>(&sWdown[h * FP]);
            #pragma unroll
            for (int q = 0; q < 13; q++) {
                ulonglong2 w = wrow[q];
                ffma2(op[2*q],   xvv, w.x);
                ffma2(op[2*q+1], xvv, w.y);
            }
        }

        // diffusion net at t=0: coef = SIGMA*sigmoid(relu(o@W1+b1)@W2+b2)*sqrt(dt)
        float ds = __ldg(b_diff2);
        #pragma unroll 4
        for (int m = 0; m < DH; m++) {
            uint64_t sp = pack2(sB1[m], 0.0f);
            const ulonglong2* wrow = reinterpret_cast<const ulonglong2*>(&sW1T[m * FP]);
            #pragma unroll
            for (int q = 0; q < 13; q++) {
                ulonglong2 w = wrow[q];
                ffma2(sp, op[2*q],   w.x);
                ffma2(sp, op[2*q+1], w.y);
            }
            float2 sv = unpack2(sp);
            float s = sv.x + sv.y;
            ds = fmaf(fmaxf(s, 0.0f), sW2[m], ds);
        }
        coef = SIG * (1.0f / (1.0f + expf(-ds))) * SQDT;
    }

    const uint64_t DT2   = pack2(DT, DT);
    const float coefs = coef * 1.41421356f;        // fold sqrt(2) into coef
    const uint64_t coef2 = pack2(coefs, coefs);

    // ---- 64 SDE steps ----
    for (int i = 0; i < 64; i++) {
        const uint32_t fk0 = sK0[i], fk1 = sK1[i];
        const uint32_t fk2 = fk0 ^ fk1 ^ 0x1BD11BDAu;
        const uint32_t kb1 = fk2 + 1u, kb2 = fk0 + 2u, kb3 = fk1 + 3u,
                       kb4 = fk2 + 4u, kb5 = fk0 + 5u;
        const uint32_t x1base = cbase + fk1;     // x1_init = (cbase+f) + k1

        // drift pre-activation (packed): accp = o @ W_drift + b_drift
        uint64_t accp[26];
        {
            const ulonglong2* bb = reinterpret_cast<const ulonglong2*>(sBdrift);
            #pragma unroll
            for (int q = 0; q < 13; q++) {
                ulonglong2 b2 = bb[q];
                accp[2*q] = b2.x; accp[2*q+1] = b2.y;
            }
        }
        #pragma unroll 5
        for (int jq = 0; jq < 25; jq++) {           // feature pair (2jq, 2jq+1)
            float2 ov = unpack2(op[jq]);
            uint64_t o0 = pack2(ov.x, ov.x);
            uint64_t o1 = pack2(ov.y, ov.y);
            const ulonglong2* w0 = reinterpret_cast<const ulonglong2*>(&sWd[(2*jq)   * FP]);
            const ulonglong2* w1 = reinterpret_cast<const ulonglong2*>(&sWd[(2*jq+1) * FP]);
            #pragma unroll
            for (int q = 0; q < 13; q++) {
                ulonglong2 wa = w0[q];
                ulonglong2 wb = w1[q];
                ffma2(accp[2*q],   o0, wa.x);
                ffma2(accp[2*q+1], o0, wa.y);
                ffma2(accp[2*q],   o1, wb.x);
                ffma2(accp[2*q+1], o1, wb.y);
            }
        }

        // noise + packed update: o += relu(acc)*DT + coef'*z'
        #pragma unroll 5
        for (int q = 0; q < 25; q++) {
            uint32_t b0 = tf_bits(fk0, fk1, fk2, kb1, kb2, kb3, kb4, kb5,
                                  x1base + (uint32_t)(2*q));
            uint32_t b1 = tf_bits(fk0, fk1, fk2, kb1, kb2, kb3, kb4, kb5,
                                  x1base + (uint32_t)(2*q) + 1u);
            float z0 = bits_to_normal_noscale(b0);
            float z1 = bits_to_normal_noscale(b1);
            float2 a = unpack2(accp[q]);
            uint64_t ap = pack2(fmaxf(a.x, 0.0f), fmaxf(a.y, 0.0f));
            ffma2(op[q], ap, DT2);
            uint64_t zp = pack2(z0, z1);
            ffma2(op[q], zp, coef2);
        }
    }

    // ---- head: final = relu(o) @ W_fc + b_fc; mu, softplus(sigma)+1e-3 ----
    float mu = __ldg(b_fc + 0);
    float sg = __ldg(b_fc + 1);
    #pragma unroll
    for (int q = 0; q < 25; q++) {
        float2 ov = unpack2(op[q]);
        float r0 = fmaxf(ov.x, 0.0f);
        float r1 = fmaxf(ov.y, 0.0f);
        mu = fmaf(r0, sWfc[4*q],     mu);
        sg = fmaf(r0, sWfc[4*q + 1], sg);
        mu = fmaf(r1, sWfc[4*q + 2], mu);
        sg = fmaf(r1, sWfc[4*q + 3], sg);
    }
    float sigma = fmaxf(sg, 0.0f) + log1pf(expf(-fabsf(sg))) + 0.001f;

    out[t] = mu;
    out[(size_t)N + t] = sigma;
}

extern "C" void kernel_launch(void* const* d_in, const int* in_sizes, int n_in,
                              void* d_out, int out_size)
{
    const float* x       = (const float*)d_in[0];
    const float* W_down  = (const float*)d_in[1];
    const float* b_down  = (const float*)d_in[2];
    const float* W_drift = (const float*)d_in[3];
    const float* b_drift = (const float*)d_in[4];
    const float* W_diff1 = (const float*)d_in[5];
    const float* b_diff1 = (const float*)d_in[6];
    const float* W_diff2 = (const float*)d_in[7];
    const float* b_diff2 = (const float*)d_in[8];
    const float* W_fc    = (const float*)d_in[9];
    const float* b_fc    = (const float*)d_in[10];

    int N = in_sizes[0] / H_IN;          // number of tokens (B*L)
    int threads = 128;
    int blocks = (N + threads - 1) / threads;

    sde_kernel<<<blocks, threads>>>(x, W_down, b_down, W_drift, b_drift,
                                    W_diff1, b_diff1, W_diff2, b_diff2,
                                    W_fc, b_fc, (float*)d_out, N);
}